// round 5
// baseline (speedup 1.0000x reference)
#include <cuda_runtime.h>
#include <math.h>

// Problem constants (fixed by the dataset)
#define VTOT 160000
#define VG   20000
#define BGR  8
#define KEIG 128
#define DCH  128

// Scratch: spectral coefficients (B,K,D) pre- and post- exp scaling.
__device__ float g_spec[BGR * KEIG * DCH];
__device__ float g_shat[BGR * KEIG * DCH];

// ---- packed f32x2 helpers (Blackwell) ----
__device__ __forceinline__ unsigned long long pack2(float x) {
    unsigned long long r;
    asm("mov.b64 %0, {%1, %1};" : "=l"(r) : "f"(x));
    return r;
}
__device__ __forceinline__ void ffma2(unsigned long long& c,
                                      unsigned long long a,
                                      unsigned long long b) {
    asm("fma.rn.f32x2 %0, %1, %2, %0;" : "+l"(c) : "l"(a), "l"(b));
}
__device__ __forceinline__ void unpack2(unsigned long long v, float& lo, float& hi) {
    asm("mov.b64 {%0, %1}, %2;" : "=f"(lo), "=f"(hi) : "l"(v));
}

// ---------------------------------------------------------------------------
// Kernel 0: zero the x_spec accumulator (run before every to-basis pass).
// ---------------------------------------------------------------------------
__global__ void zero_spec_kernel() {
    int i = blockIdx.x * blockDim.x + threadIdx.x;
    if (i < BGR * KEIG * DCH) g_spec[i] = 0.0f;
}

// ---------------------------------------------------------------------------
// Kernel A (to_basis): g_spec[b,k,d] += sum_v evecs[b,v,k]*mass[b,v]*x[b,v,d]
// Block = 256 threads, computes the full 128x128 (K x D) tile for one graph
// over a 544-row chunk of V; partial sums merged with atomicAdd (REDG).
// Grid = (37 chunks, 8 graphs) = 296 blocks = one full wave at 2 CTA/SM.
// ---------------------------------------------------------------------------
#define CHUNK 544
#define NSTEP 34   // 34 * 16 = 544

__global__ __launch_bounds__(256, 2)
void gemm_tobasis(const float* __restrict__ x,
                  const float* __restrict__ mass,
                  const float* __restrict__ evecs) {
    __shared__ float sA[16][128];  // (evecs * mass)[v-step][k]
    __shared__ float sB[16][128];  // x[v-step][d]

    const int b   = blockIdx.y;
    const int v0  = blockIdx.x * CHUNK;
    const int tid = threadIdx.x;
    const int tx  = tid & 15;      // D micro-tile group
    const int ty  = tid >> 4;      // K micro-tile group
    const int gbase = b * VG;

    unsigned long long acc[8][4];
#pragma unroll
    for (int i = 0; i < 8; i++)
#pragma unroll
        for (int j = 0; j < 4; j++) acc[i][j] = 0ull;

    for (int s = 0; s < NSTEP; s++) {
        const int vstep = v0 + s * 16;
        __syncthreads();
        // stage 16x128 of each operand (2 float4 per thread per operand)
#pragma unroll
        for (int r = 0; r < 2; r++) {
            int slot = tid + r * 256;      // 512 float4 slots
            int row  = slot >> 5;          // 0..15
            int c4   = slot & 31;          // 0..31 (float4 column)
            int v    = vstep + row;
            float4 av = make_float4(0.f, 0.f, 0.f, 0.f);
            float4 bv = make_float4(0.f, 0.f, 0.f, 0.f);
            if (v < VG) {
                int gv = gbase + v;
                av = *(const float4*)(evecs + (size_t)gv * KEIG + c4 * 4);
                float m = mass[gv];
                av.x *= m; av.y *= m; av.z *= m; av.w *= m;
                bv = *(const float4*)(x + (size_t)gv * DCH + c4 * 4);
            }
            *(float4*)&sA[row][c4 * 4] = av;
            *(float4*)&sB[row][c4 * 4] = bv;
        }
        __syncthreads();

#pragma unroll
        for (int kk = 0; kk < 16; kk++) {
            float4 a0 = *(const float4*)&sA[kk][ty * 8];
            float4 a1 = *(const float4*)&sA[kk][ty * 8 + 4];
            unsigned long long ap[8];
            ap[0] = pack2(a0.x); ap[1] = pack2(a0.y);
            ap[2] = pack2(a0.z); ap[3] = pack2(a0.w);
            ap[4] = pack2(a1.x); ap[5] = pack2(a1.y);
            ap[6] = pack2(a1.z); ap[7] = pack2(a1.w);
            const unsigned long long* bp =
                (const unsigned long long*)&sB[kk][tx * 8];
            unsigned long long bb[4] = {bp[0], bp[1], bp[2], bp[3]};
#pragma unroll
            for (int i = 0; i < 8; i++)
#pragma unroll
                for (int j = 0; j < 4; j++) ffma2(acc[i][j], ap[i], bb[j]);
        }
    }

    // epilogue: atomic reduction into g_spec[b,k,d]
    float* dst = g_spec + b * (KEIG * DCH);
#pragma unroll
    for (int i = 0; i < 8; i++) {
        int krow = ty * 8 + i;
#pragma unroll
        for (int j = 0; j < 4; j++) {
            float lo, hi;
            unpack2(acc[i][j], lo, hi);
            atomicAdd(&dst[krow * DCH + tx * 8 + j * 2],     lo);
            atomicAdd(&dst[krow * DCH + tx * 8 + j * 2 + 1], hi);
        }
    }
}

// ---------------------------------------------------------------------------
// Kernel B: g_shat[b,k,d] = g_spec[b,k,d] * exp(-evals[b*K+k] * max(t[d],1e-8))
// ---------------------------------------------------------------------------
__global__ void spectral_scale(const float* __restrict__ evals,
                               const float* __restrict__ tdiff) {
    int i = blockIdx.x * blockDim.x + threadIdx.x;
    if (i >= BGR * KEIG * DCH) return;
    int d  = i & (DCH - 1);
    int bk = i >> 7;  // b*K + k
    float t   = fmaxf(tdiff[d], 1e-8f);
    float lam = evals[bk];
    g_shat[i] = g_spec[i] * expf(-lam * t);
}

// ---------------------------------------------------------------------------
// Kernel C (from_basis): out[b,v,d] = sum_k evecs[b,v,k] * g_shat[b,k,d]
// Block = 256 threads, 128-row x 128-col tile. E tile staged TRANSPOSED
// ([k][v]) so a-reads are contiguous float4; S tile staged directly ([k][d]).
// Grid = (157 row-tiles, 8 graphs).
// ---------------------------------------------------------------------------
__global__ __launch_bounds__(256, 2)
void gemm_frombasis(const float* __restrict__ evecs,
                    float* __restrict__ out) {
    __shared__ float sSt[16][128];   // s_hat[k-step][d]
    __shared__ float sEt[16][132];   // evecs transposed [k-step][v], padded

    const int b   = blockIdx.y;
    const int v0  = blockIdx.x * 128;
    const int tid = threadIdx.x;
    const int tx  = tid & 15;        // D group
    const int ty  = tid >> 4;        // V group
    const float* sh = g_shat + b * (KEIG * DCH);

    unsigned long long acc[8][4];
#pragma unroll
    for (int i = 0; i < 8; i++)
#pragma unroll
        for (int j = 0; j < 4; j++) acc[i][j] = 0ull;

    for (int kb = 0; kb < 8; kb++) {
        __syncthreads();
        // stage S tile: rows kb*16 .. kb*16+15 of (K x D)
#pragma unroll
        for (int r = 0; r < 2; r++) {
            int slot = tid + r * 256;    // 512 float4 slots
            int row  = slot >> 5;        // 0..15
            int c4   = slot & 31;
            *(float4*)&sSt[row][c4 * 4] =
                *(const float4*)(sh + (kb * 16 + row) * DCH + c4 * 4);
        }
        // stage E tile transposed: (128 v-rows) x (16 k) -> sEt[k][v]
#pragma unroll
        for (int r = 0; r < 2; r++) {
            int slot = tid + r * 256;    // 512 float4 slots
            int vrow = slot >> 2;        // 0..127
            int k4   = slot & 3;         // 0..3
            int v    = v0 + vrow;
            float4 ev = make_float4(0.f, 0.f, 0.f, 0.f);
            if (v < VG)
                ev = *(const float4*)(evecs + (size_t)(b * VG + v) * KEIG
                                      + kb * 16 + k4 * 4);
            sEt[k4 * 4 + 0][vrow] = ev.x;
            sEt[k4 * 4 + 1][vrow] = ev.y;
            sEt[k4 * 4 + 2][vrow] = ev.z;
            sEt[k4 * 4 + 3][vrow] = ev.w;
        }
        __syncthreads();

#pragma unroll
        for (int kk = 0; kk < 16; kk++) {
            float4 a0 = *(const float4*)&sEt[kk][ty * 8];
            float4 a1 = *(const float4*)&sEt[kk][ty * 8 + 4];
            unsigned long long ap[8];
            ap[0] = pack2(a0.x); ap[1] = pack2(a0.y);
            ap[2] = pack2(a0.z); ap[3] = pack2(a0.w);
            ap[4] = pack2(a1.x); ap[5] = pack2(a1.y);
            ap[6] = pack2(a1.z); ap[7] = pack2(a1.w);
            const unsigned long long* bp =
                (const unsigned long long*)&sSt[kk][tx * 8];
            unsigned long long bb[4] = {bp[0], bp[1], bp[2], bp[3]};
#pragma unroll
            for (int i = 0; i < 8; i++)
#pragma unroll
                for (int j = 0; j < 4; j++) ffma2(acc[i][j], ap[i], bb[j]);
        }
    }

    // store: out[(b*VG+v)*D + d]
#pragma unroll
    for (int i = 0; i < 8; i++) {
        int v = v0 + ty * 8 + i;
        if (v < VG) {
            float* o = out + (size_t)(b * VG + v) * DCH + tx * 8;
#pragma unroll
            for (int j = 0; j < 4; j++) {
                float lo, hi;
                unpack2(acc[i][j], lo, hi);
                o[j * 2]     = lo;
                o[j * 2 + 1] = hi;
            }
        }
    }
}

// ---------------------------------------------------------------------------
// Launch
// Inputs (metadata order): 0:x (V,D) f32, 1:mass (V,) f32, 2:evals (B*K,) f32,
// 3:evecs (V,K) f32, 4:diffusion_time (D,) f32, 5:batch (V,) i32, 6:bs
// Output: (V,D) f32
// ---------------------------------------------------------------------------
extern "C" void kernel_launch(void* const* d_in, const int* in_sizes, int n_in,
                              void* d_out, int out_size) {
    const float* x     = (const float*)d_in[0];
    const float* mass  = (const float*)d_in[1];
    const float* evals = (const float*)d_in[2];
    const float* evecs = (const float*)d_in[3];
    const float* tdiff = (const float*)d_in[4];
    float* out = (float*)d_out;

    (void)in_sizes; (void)n_in; (void)out_size;

    // 1) zero the spectral accumulator
    zero_spec_kernel<<<(BGR * KEIG * DCH + 255) / 256, 256>>>();

    // 2) to_basis: 37 chunks x 8 graphs
    dim3 gridA(37, BGR);
    gemm_tobasis<<<gridA, 256>>>(x, mass, evecs);

    // 3) spectral diffusion scaling
    spectral_scale<<<(BGR * KEIG * DCH + 255) / 256, 256>>>(evals, tdiff);

    // 4) from_basis: 157 row-tiles x 8 graphs
    dim3 gridC((VG + 127) / 128, BGR);
    gemm_frombasis<<<gridC, 256>>>(evecs, out);
}

// round 7
// speedup vs baseline: 2.3027x; 2.3027x over previous
#include <cuda_runtime.h>
#include <cstdint>
#include <math.h>

// Problem constants (fixed by the dataset)
#define VG   20000
#define BGR  8
#define KEIG 128
#define DCH  128

#define NCHUNK   32
#define TB_CHUNK 640     // 32 * 640 = 20480 >= 20000
#define TB_P     68      // transposed-tile pitch (floats): conflict-free frag reads
#define FB_P     132     // K-major tile pitch (floats): conflict-free frag reads

// Scratch (device globals — no allocations)
__device__ float g_part[BGR * NCHUNK * KEIG * DCH];  // per-chunk partial x_spec
__device__ float g_shat_T[BGR * DCH * KEIG];         // scaled spectrum, [b][d][k]

// ---------------------------------------------------------------------------
// helpers
// ---------------------------------------------------------------------------
__device__ __forceinline__ uint32_t f2tf32(float x) {
    uint32_t r;
    asm("cvt.rna.tf32.f32 %0, %1;" : "=r"(r) : "f"(x));
    return r;
}

// m16n8k8 tf32 mma (legacy tensor path — baseline PTX, works on sm_103)
__device__ __forceinline__ void mma8(float c[4], const uint32_t a[4],
                                     const uint32_t b[2]) {
    asm volatile(
        "mma.sync.aligned.m16n8k8.row.col.f32.tf32.tf32.f32 "
        "{%0,%1,%2,%3}, {%4,%5,%6,%7}, {%8,%9}, {%0,%1,%2,%3};"
        : "+f"(c[0]), "+f"(c[1]), "+f"(c[2]), "+f"(c[3])
        : "r"(a[0]), "r"(a[1]), "r"(a[2]), "r"(a[3]),
          "r"(b[0]), "r"(b[1]));
}

// ---------------------------------------------------------------------------
// Kernel A (to_basis): g_part[b,chunk,k,d] = sum_{v in chunk} (E[v,k]*m[v]) * X[v,d]
// 256 threads = 8 warps (2 x 4); warp tile 64(k) x 32(d); m16n8k8 frags.
// Contraction dim is v -> stage both operands transposed: sE[k][v], sX[d][v].
// ---------------------------------------------------------------------------
__global__ __launch_bounds__(256)
void gemm_tobasis_tc(const float* __restrict__ x,
                     const float* __restrict__ mass,
                     const float* __restrict__ evecs) {
    extern __shared__ uint32_t sm[];
    uint32_t* sE = sm;                  // [KEIG][TB_P]
    uint32_t* sX = sm + KEIG * TB_P;    // [DCH][TB_P]

    const int b     = blockIdx.y;
    const int chunk = blockIdx.x;
    const int cbase = chunk * TB_CHUNK;
    const int tid   = threadIdx.x;
    const int lane  = tid & 31;
    const int wid   = tid >> 5;
    const int m0    = (wid & 1) * 64;   // k-eig offset
    const int n0    = (wid >> 1) * 32;  // d offset
    const int g     = lane >> 2;
    const int t     = lane & 3;

    const float* Eb = evecs + (size_t)b * VG * KEIG;
    const float* Xb = x     + (size_t)b * VG * DCH;
    const float* Mb = mass  + (size_t)b * VG;

    float c[4][4][4];
#pragma unroll
    for (int mi = 0; mi < 4; mi++)
#pragma unroll
        for (int ni = 0; ni < 4; ni++)
#pragma unroll
            for (int q = 0; q < 4; q++) c[mi][ni][q] = 0.f;

    for (int s = 0; s < TB_CHUNK / 64; s++) {
        const int sv = cbase + s * 64;
        __syncthreads();
        // stage 64 v-rows of E (x mass) and X, transposed into [k][v]
#pragma unroll
        for (int r = 0; r < 8; r++) {
            int idx = r * 256 + tid;
            int k4  = (idx & 7) | ((idx >> 9) << 3);  // 0..31
            int v   = (idx >> 3) & 63;
            int gv  = sv + v;
            float4 ev = make_float4(0.f, 0.f, 0.f, 0.f);
            float4 xv = make_float4(0.f, 0.f, 0.f, 0.f);
            float  m  = 0.f;
            if (gv < VG) {
                ev = *(const float4*)(Eb + (size_t)gv * KEIG + k4 * 4);
                xv = *(const float4*)(Xb + (size_t)gv * DCH  + k4 * 4);
                m  = Mb[gv];
            }
            uint32_t* pe = sE + (k4 * 4) * TB_P + v;
            pe[0]          = f2tf32(ev.x * m);
            pe[TB_P]       = f2tf32(ev.y * m);
            pe[2 * TB_P]   = f2tf32(ev.z * m);
            pe[3 * TB_P]   = f2tf32(ev.w * m);
            uint32_t* px = sX + (k4 * 4) * TB_P + v;
            px[0]          = f2tf32(xv.x);
            px[TB_P]       = f2tf32(xv.y);
            px[2 * TB_P]   = f2tf32(xv.z);
            px[3 * TB_P]   = f2tf32(xv.w);
        }
        __syncthreads();

#pragma unroll
        for (int kv = 0; kv < 64; kv += 8) {
            uint32_t af[4][4], bf[4][2];
#pragma unroll
            for (int mi = 0; mi < 4; mi++) {
                const uint32_t* p = sE + (m0 + mi * 16 + g) * TB_P + kv + t;
                af[mi][0] = p[0];
                af[mi][1] = p[8 * TB_P];
                af[mi][2] = p[4];
                af[mi][3] = p[8 * TB_P + 4];
            }
#pragma unroll
            for (int ni = 0; ni < 4; ni++) {
                const uint32_t* p = sX + (n0 + ni * 8 + g) * TB_P + kv + t;
                bf[ni][0] = p[0];
                bf[ni][1] = p[4];
            }
#pragma unroll
            for (int mi = 0; mi < 4; mi++)
#pragma unroll
                for (int ni = 0; ni < 4; ni++) mma8(c[mi][ni], af[mi], bf[ni]);
        }
    }

    // epilogue: private partial slab, plain stores
    float* dst = g_part + ((size_t)(b * NCHUNK + chunk) << 14);
#pragma unroll
    for (int mi = 0; mi < 4; mi++) {
        int r0 = m0 + mi * 16 + g;
#pragma unroll
        for (int ni = 0; ni < 4; ni++) {
            int col = n0 + ni * 8 + 2 * t;
            *(float2*)&dst[r0 * DCH + col] =
                make_float2(c[mi][ni][0], c[mi][ni][1]);
            *(float2*)&dst[(r0 + 8) * DCH + col] =
                make_float2(c[mi][ni][2], c[mi][ni][3]);
        }
    }
}

// ---------------------------------------------------------------------------
// Kernel B: reduce 32 partials + exp scale; write transposed [b][d][k]
// ---------------------------------------------------------------------------
__global__ void spectral_reduce_scale(const float* __restrict__ evals,
                                      const float* __restrict__ tdiff) {
    int i = blockIdx.x * 256 + threadIdx.x;   // over b*K*D
    if (i >= BGR * KEIG * DCH) return;
    int d = i & 127;
    int k = (i >> 7) & 127;
    int b = i >> 14;
    const float* p = g_part + ((size_t)(b * NCHUNK) << 14) + k * DCH + d;
    float s = 0.f;
#pragma unroll
    for (int ch = 0; ch < NCHUNK; ch++) s += p[(size_t)ch << 14];
    float tt = fmaxf(tdiff[d], 1e-8f);
    g_shat_T[(b << 14) + (d << 7) + k] = s * expf(-evals[b * KEIG + k] * tt);
}

// ---------------------------------------------------------------------------
// Kernel C (from_basis): out[v,d] = sum_k E[v,k] * S_T[d,k]
// Both operands K-major -> direct staged copies. 128x128x128 per CTA.
// ---------------------------------------------------------------------------
__global__ __launch_bounds__(256)
void gemm_frombasis_tc(const float* __restrict__ evecs,
                       float* __restrict__ out) {
    extern __shared__ uint32_t sm[];
    uint32_t* sE = sm;                  // [128 v][FB_P]
    uint32_t* sS = sm + 128 * FB_P;     // [128 d][FB_P]

    const int b    = blockIdx.y;
    const int v0   = blockIdx.x * 128;
    const int tid  = threadIdx.x;
    const int lane = tid & 31;
    const int wid  = tid >> 5;
    const int m0   = (wid & 1) * 64;    // v offset
    const int n0   = (wid >> 1) * 32;   // d offset
    const int g    = lane >> 2;
    const int t    = lane & 3;

    const float* Eb = evecs    + (size_t)b * VG * KEIG;
    const float* Sb = g_shat_T + ((size_t)b << 14);

#pragma unroll
    for (int r = 0; r < 16; r++) {
        int idx = r * 256 + tid;
        int row = idx >> 5;
        int k4  = idx & 31;
        float4 s4 = *(const float4*)(Sb + (size_t)row * KEIG + k4 * 4);
        uint32_t* ps = sS + row * FB_P + k4 * 4;
        ps[0] = f2tf32(s4.x); ps[1] = f2tf32(s4.y);
        ps[2] = f2tf32(s4.z); ps[3] = f2tf32(s4.w);
        int v = v0 + row;
        float4 e4 = (v < VG)
            ? *(const float4*)(Eb + (size_t)v * KEIG + k4 * 4)
            : make_float4(0.f, 0.f, 0.f, 0.f);
        uint32_t* pe = sE + row * FB_P + k4 * 4;
        pe[0] = f2tf32(e4.x); pe[1] = f2tf32(e4.y);
        pe[2] = f2tf32(e4.z); pe[3] = f2tf32(e4.w);
    }
    __syncthreads();

    float c[4][4][4];
#pragma unroll
    for (int mi = 0; mi < 4; mi++)
#pragma unroll
        for (int ni = 0; ni < 4; ni++)
#pragma unroll
            for (int q = 0; q < 4; q++) c[mi][ni][q] = 0.f;

#pragma unroll 4
    for (int ks = 0; ks < 128; ks += 8) {
        uint32_t af[4][4], bf[4][2];
#pragma unroll
        for (int mi = 0; mi < 4; mi++) {
            const uint32_t* p = sE + (m0 + mi * 16 + g) * FB_P + ks + t;
            af[mi][0] = p[0];
            af[mi][1] = p[8 * FB_P];
            af[mi][2] = p[4];
            af[mi][3] = p[8 * FB_P + 4];
        }
#pragma unroll
        for (int ni = 0; ni < 4; ni++) {
            const uint32_t* p = sS + (n0 + ni * 8 + g) * FB_P + ks + t;
            bf[ni][0] = p[0];
            bf[ni][1] = p[4];
        }
#pragma unroll
        for (int mi = 0; mi < 4; mi++)
#pragma unroll
            for (int ni = 0; ni < 4; ni++) mma8(c[mi][ni], af[mi], bf[ni]);
    }

    // epilogue: direct, sector-aligned float2 stores
#pragma unroll
    for (int mi = 0; mi < 4; mi++) {
        int vlo = v0 + m0 + mi * 16 + g;
#pragma unroll
        for (int ni = 0; ni < 4; ni++) {
            int col = n0 + ni * 8 + 2 * t;
            if (vlo < VG)
                *(float2*)(out + (size_t)(b * VG + vlo) * DCH + col) =
                    make_float2(c[mi][ni][0], c[mi][ni][1]);
            if (vlo + 8 < VG)
                *(float2*)(out + (size_t)(b * VG + vlo + 8) * DCH + col) =
                    make_float2(c[mi][ni][2], c[mi][ni][3]);
        }
    }
}

// ---------------------------------------------------------------------------
// Launch
// Inputs: 0:x (V,D) f32, 1:mass (V,) f32, 2:evals (B*K,) f32,
// 3:evecs (V,K) f32, 4:diffusion_time (D,) f32, 5:batch (V,) i32, 6:bs
// Output: (V,D) f32
// ---------------------------------------------------------------------------
extern "C" void kernel_launch(void* const* d_in, const int* in_sizes, int n_in,
                              void* d_out, int out_size) {
    const float* x     = (const float*)d_in[0];
    const float* mass  = (const float*)d_in[1];
    const float* evals = (const float*)d_in[2];
    const float* evecs = (const float*)d_in[3];
    const float* tdiff = (const float*)d_in[4];
    float* out = (float*)d_out;

    (void)in_sizes; (void)n_in; (void)out_size;

    const int TB_SMEM = 2 * KEIG * TB_P * 4;   // 69632 B
    const int FB_SMEM = 2 * 128 * FB_P * 4;    // 135168 B
    cudaFuncSetAttribute(gemm_tobasis_tc,
                         cudaFuncAttributeMaxDynamicSharedMemorySize, TB_SMEM);
    cudaFuncSetAttribute(gemm_frombasis_tc,
                         cudaFuncAttributeMaxDynamicSharedMemorySize, FB_SMEM);

    dim3 gridA(NCHUNK, BGR);
    gemm_tobasis_tc<<<gridA, 256, TB_SMEM>>>(x, mass, evecs);

    spectral_reduce_scale<<<(BGR * KEIG * DCH + 255) / 256, 256>>>(evals, tdiff);

    dim3 gridC((VG + 127) / 128, BGR);
    gemm_frombasis_tc<<<gridC, 256, FB_SMEM>>>(evecs, out);
}

// round 8
// speedup vs baseline: 2.8756x; 1.2488x over previous
#include <cuda_runtime.h>
#include <cstdint>
#include <math.h>

// Problem constants (fixed by the dataset)
#define VG   20000
#define BGR  8
#define KEIG 128
#define DCH  128

#define NCHUNK   37      // 37 chunks x 8 graphs = 296 CTAs = one 2-CTA/SM wave
#define TB_CHUNK 544     // 37 * 544 = 20128 >= 20000
#define TB_ROWS  32      // v-rows per stage
#define TB_NS    17      // stages per chunk (17*32 = 544)
#define TB_PITCH 136     // 136 mod 32 == 8 -> conflict-free (t*pitch+g) frag reads
#define FB_PITCH 68      // 68 mod 32 == 4 -> conflict-free (g*pitch+t) frag reads

// Scratch (device globals — no allocations)
__device__ float g_part[BGR * NCHUNK * KEIG * DCH];  // per-chunk partial x_spec
__device__ float g_shat_T[BGR * DCH * KEIG];         // scaled spectrum, [b][d][k]

// ---------------------------------------------------------------------------
// helpers
// ---------------------------------------------------------------------------
__device__ __forceinline__ uint32_t f2tf32(float x) {
    uint32_t r;
    asm("cvt.rna.tf32.f32 %0, %1;" : "=r"(r) : "f"(x));
    return r;
}

__device__ __forceinline__ void mma8(float c[4], const uint32_t a[4],
                                     const uint32_t b[2]) {
    asm volatile(
        "mma.sync.aligned.m16n8k8.row.col.f32.tf32.tf32.f32 "
        "{%0,%1,%2,%3}, {%4,%5,%6,%7}, {%8,%9}, {%0,%1,%2,%3};"
        : "+f"(c[0]), "+f"(c[1]), "+f"(c[2]), "+f"(c[3])
        : "r"(a[0]), "r"(a[1]), "r"(a[2]), "r"(a[3]),
          "r"(b[0]), "r"(b[1]));
}

__device__ __forceinline__ uint32_t pack_cvt_store4(uint32_t* dst, float4 v) {
    // cvt 4 lanes to tf32 and store as one 16B STS (conflict-free row copy)
    uint4 u;
    u.x = f2tf32(v.x); u.y = f2tf32(v.y); u.z = f2tf32(v.z); u.w = f2tf32(v.w);
    *(uint4*)dst = u;
    return 0;
}

// ---------------------------------------------------------------------------
// Kernel A (to_basis): g_part[b,chunk,k,d] = sum_{v in chunk} (E[v,k]*m[v]) * X[v,d]
// Untransposed staging: sE[v][keig], sX[v][d], pitch 136 (conflict-free both
// for STS.128 staging and (t*pitch+g) frag reads). 32-row stages.
// ---------------------------------------------------------------------------
__global__ __launch_bounds__(256, 2)
void gemm_tobasis_tc(const float* __restrict__ x,
                     const float* __restrict__ mass,
                     const float* __restrict__ evecs) {
    __shared__ uint32_t sE[TB_ROWS * TB_PITCH];
    __shared__ uint32_t sX[TB_ROWS * TB_PITCH];

    const int b     = blockIdx.y;
    const int cbase = blockIdx.x * TB_CHUNK;
    const int tid   = threadIdx.x;
    const int lane  = tid & 31;
    const int wid   = tid >> 5;
    const int m0    = (wid & 1) * 64;   // k-eig offset
    const int n0    = (wid >> 1) * 32;  // d offset
    const int g     = lane >> 2;
    const int t     = lane & 3;

    const float* Eb = evecs + (size_t)b * VG * KEIG;
    const float* Xb = x     + (size_t)b * VG * DCH;
    const float* Mb = mass  + (size_t)b * VG;

    float c[4][4][4];
#pragma unroll
    for (int mi = 0; mi < 4; mi++)
#pragma unroll
        for (int ni = 0; ni < 4; ni++)
#pragma unroll
            for (int q = 0; q < 4; q++) c[mi][ni][q] = 0.f;

    for (int s = 0; s < TB_NS; s++) {
        const int sv = cbase + s * TB_ROWS;
        __syncthreads();
        // stage 32 v-rows of E*mass and X: 4 float4 per op per thread
#pragma unroll
        for (int r = 0; r < 4; r++) {
            int idx = r * 256 + tid;          // 0..1023
            int row = idx >> 5;               // 0..31
            int c4  = idx & 31;               // 0..31
            int gv  = sv + row;
            float4 ev = make_float4(0.f, 0.f, 0.f, 0.f);
            float4 xv = make_float4(0.f, 0.f, 0.f, 0.f);
            if (gv < VG) {
                ev = *(const float4*)(Eb + (size_t)gv * KEIG + c4 * 4);
                float m = Mb[gv];
                ev.x *= m; ev.y *= m; ev.z *= m; ev.w *= m;
                xv = *(const float4*)(Xb + (size_t)gv * DCH + c4 * 4);
            }
            pack_cvt_store4(sE + row * TB_PITCH + c4 * 4, ev);
            pack_cvt_store4(sX + row * TB_PITCH + c4 * 4, xv);
        }
        __syncthreads();

#pragma unroll
        for (int kv = 0; kv < TB_ROWS; kv += 8) {
            const uint32_t* eLo = sE + (kv + t) * TB_PITCH;
            const uint32_t* eHi = sE + (kv + t + 4) * TB_PITCH;
            const uint32_t* xLo = sX + (kv + t) * TB_PITCH;
            const uint32_t* xHi = sX + (kv + t + 4) * TB_PITCH;
            uint32_t af[4][4], bf[4][2];
#pragma unroll
            for (int mi = 0; mi < 4; mi++) {
                int mIdx = m0 + mi * 16 + g;
                af[mi][0] = eLo[mIdx];
                af[mi][1] = eLo[mIdx + 8];
                af[mi][2] = eHi[mIdx];
                af[mi][3] = eHi[mIdx + 8];
            }
#pragma unroll
            for (int ni = 0; ni < 4; ni++) {
                int nIdx = n0 + ni * 8 + g;
                bf[ni][0] = xLo[nIdx];
                bf[ni][1] = xHi[nIdx];
            }
#pragma unroll
            for (int mi = 0; mi < 4; mi++)
#pragma unroll
                for (int ni = 0; ni < 4; ni++) mma8(c[mi][ni], af[mi], bf[ni]);
        }
    }

    // epilogue: private partial slab, plain stores
    float* dst = g_part + ((size_t)(b * NCHUNK + blockIdx.x) << 14);
#pragma unroll
    for (int mi = 0; mi < 4; mi++) {
        int r0 = m0 + mi * 16 + g;
#pragma unroll
        for (int ni = 0; ni < 4; ni++) {
            int col = n0 + ni * 8 + 2 * t;
            *(float2*)&dst[r0 * DCH + col] =
                make_float2(c[mi][ni][0], c[mi][ni][1]);
            *(float2*)&dst[(r0 + 8) * DCH + col] =
                make_float2(c[mi][ni][2], c[mi][ni][3]);
        }
    }
}

// ---------------------------------------------------------------------------
// Kernel B: reduce NCHUNK partials + exp scale; write transposed [b][d][k]
// ---------------------------------------------------------------------------
__global__ void spectral_reduce_scale(const float* __restrict__ evals,
                                      const float* __restrict__ tdiff) {
    int i = blockIdx.x * 256 + threadIdx.x;   // over b*K*D
    if (i >= BGR * KEIG * DCH) return;
    int d = i & 127;
    int k = (i >> 7) & 127;
    int b = i >> 14;
    const float* p = g_part + ((size_t)(b * NCHUNK) << 14) + k * DCH + d;
    float s = 0.f;
#pragma unroll
    for (int ch = 0; ch < NCHUNK; ch++) s += p[(size_t)ch << 14];
    float tt = fmaxf(tdiff[d], 1e-8f);
    g_shat_T[(b << 14) + (d << 7) + k] = s * expf(-evals[b * KEIG + k] * tt);
}

// ---------------------------------------------------------------------------
// Kernel C (from_basis): out[v,d] = sum_k E[v,k] * S_T[d,k]
// Two 64-wide k-halves, pitch 68 -> 69.6KB smem -> 2 CTA/SM for cross-CTA
// latency hiding across the 4.2 waves.
// ---------------------------------------------------------------------------
__global__ __launch_bounds__(256, 2)
void gemm_frombasis_tc(const float* __restrict__ evecs,
                       float* __restrict__ out) {
    extern __shared__ uint32_t sm[];
    uint32_t* sE = sm;                      // [128 v][FB_PITCH]
    uint32_t* sS = sm + 128 * FB_PITCH;     // [128 d][FB_PITCH]

    const int b    = blockIdx.y;
    const int v0   = blockIdx.x * 128;
    const int tid  = threadIdx.x;
    const int lane = tid & 31;
    const int wid  = tid >> 5;
    const int m0   = (wid & 1) * 64;    // v offset
    const int n0   = (wid >> 1) * 32;   // d offset
    const int g    = lane >> 2;
    const int t    = lane & 3;

    const float* Eb = evecs    + (size_t)b * VG * KEIG;
    const float* Sb = g_shat_T + ((size_t)b << 14);

    float c[4][4][4];
#pragma unroll
    for (int mi = 0; mi < 4; mi++)
#pragma unroll
        for (int ni = 0; ni < 4; ni++)
#pragma unroll
            for (int q = 0; q < 4; q++) c[mi][ni][q] = 0.f;

#pragma unroll
    for (int kh = 0; kh < 2; kh++) {
        const int k0 = kh * 64;
        if (kh) __syncthreads();
        // stage: per op 128 rows x 16 float4 -> 8 float4/thread
#pragma unroll
        for (int r = 0; r < 8; r++) {
            int idx = r * 256 + tid;          // 0..2047
            int row = idx >> 4;               // 0..127
            int c4  = idx & 15;               // 0..15
            float4 s4 = *(const float4*)(Sb + (size_t)row * KEIG + k0 + c4 * 4);
            pack_cvt_store4(sS + row * FB_PITCH + c4 * 4, s4);
            int v = v0 + row;
            float4 e4 = (v < VG)
                ? *(const float4*)(Eb + (size_t)v * KEIG + k0 + c4 * 4)
                : make_float4(0.f, 0.f, 0.f, 0.f);
            pack_cvt_store4(sE + row * FB_PITCH + c4 * 4, e4);
        }
        __syncthreads();

#pragma unroll
        for (int ks = 0; ks < 64; ks += 8) {
            uint32_t af[4][4], bf[4][2];
#pragma unroll
            for (int mi = 0; mi < 4; mi++) {
                const uint32_t* p = sE + (m0 + mi * 16 + g) * FB_PITCH + ks + t;
                af[mi][0] = p[0];
                af[mi][1] = p[8 * FB_PITCH];
                af[mi][2] = p[4];
                af[mi][3] = p[8 * FB_PITCH + 4];
            }
#pragma unroll
            for (int ni = 0; ni < 4; ni++) {
                const uint32_t* p = sS + (n0 + ni * 8 + g) * FB_PITCH + ks + t;
                bf[ni][0] = p[0];
                bf[ni][1] = p[4];
            }
#pragma unroll
            for (int mi = 0; mi < 4; mi++)
#pragma unroll
                for (int ni = 0; ni < 4; ni++) mma8(c[mi][ni], af[mi], bf[ni]);
        }
    }

    // epilogue: direct, sector-aligned float2 stores
#pragma unroll
    for (int mi = 0; mi < 4; mi++) {
        int vlo = v0 + m0 + mi * 16 + g;
#pragma unroll
        for (int ni = 0; ni < 4; ni++) {
            int col = n0 + ni * 8 + 2 * t;
            if (vlo < VG)
                *(float2*)(out + (size_t)(b * VG + vlo) * DCH + col) =
                    make_float2(c[mi][ni][0], c[mi][ni][1]);
            if (vlo + 8 < VG)
                *(float2*)(out + (size_t)(b * VG + vlo + 8) * DCH + col) =
                    make_float2(c[mi][ni][2], c[mi][ni][3]);
        }
    }
}

// ---------------------------------------------------------------------------
// Launch
// Inputs: 0:x (V,D) f32, 1:mass (V,) f32, 2:evals (B*K,) f32,
// 3:evecs (V,K) f32, 4:diffusion_time (D,) f32, 5:batch (V,) i32, 6:bs
// Output: (V,D) f32
// ---------------------------------------------------------------------------
extern "C" void kernel_launch(void* const* d_in, const int* in_sizes, int n_in,
                              void* d_out, int out_size) {
    const float* x     = (const float*)d_in[0];
    const float* mass  = (const float*)d_in[1];
    const float* evals = (const float*)d_in[2];
    const float* evecs = (const float*)d_in[3];
    const float* tdiff = (const float*)d_in[4];
    float* out = (float*)d_out;

    (void)in_sizes; (void)n_in; (void)out_size;

    const int FB_SMEM = 2 * 128 * FB_PITCH * 4;   // 69632 B -> 2 CTA/SM
    cudaFuncSetAttribute(gemm_frombasis_tc,
                         cudaFuncAttributeMaxDynamicSharedMemorySize, FB_SMEM);

    dim3 gridA(NCHUNK, BGR);
    gemm_tobasis_tc<<<gridA, 256>>>(x, mass, evecs);

    spectral_reduce_scale<<<(BGR * KEIG * DCH + 255) / 256, 256>>>(evals, tdiff);

    dim3 gridC((VG + 127) / 128, BGR);
    gemm_frombasis_tc<<<gridC, 256, FB_SMEM>>>(evecs, out);
}

// round 9
// speedup vs baseline: 3.2399x; 1.1267x over previous
#include <cuda_runtime.h>
#include <cstdint>
#include <math.h>

// Problem constants (fixed by the dataset)
#define VG   20000
#define BGR  8
#define KEIG 128
#define DCH  128

#define NCHUNK   37      // 37 chunks x 8 graphs = 296 CTAs = one 2-CTA/SM wave
#define TB_CHUNK 544     // 37 * 544 = 20128 >= 20000
#define TB_ROWS  32      // v-rows per stage
#define TB_NS    17      // stages per chunk
#define TB_P     136     // pitch: conflict-free (t*136+g) frag reads + row staging

#define FB_KC    32      // k per chunk in from_basis
#define FB_P     36      // pitch: conflict-free (g*36+t) frag reads + row staging

// Scratch (device globals — no allocations)
__device__ float g_part[BGR * NCHUNK * KEIG * DCH];  // per-chunk partial x_spec
__device__ float g_shat_T[BGR * DCH * KEIG];         // scaled spectrum, tf32 bits, [b][d][k]

// ---------------------------------------------------------------------------
// helpers
// ---------------------------------------------------------------------------
__device__ __forceinline__ uint32_t f2tf32(float x) {
    uint32_t r;
    asm("cvt.rna.tf32.f32 %0, %1;" : "=r"(r) : "f"(x));
    return r;
}
__device__ __forceinline__ uint32_t smem_u32(const void* p) {
    uint32_t a;
    asm("{ .reg .u64 t; cvta.to.shared.u64 t, %1; cvt.u32.u64 %0, t; }"
        : "=r"(a) : "l"(p));
    return a;
}
// 16B async copy, zero-fill when pred==false (src must still be a valid ptr)
__device__ __forceinline__ void cpa16(uint32_t dst, const void* src, bool pred) {
    int sz = pred ? 16 : 0;
    asm volatile("cp.async.cg.shared.global [%0], [%1], 16, %2;"
                 :: "r"(dst), "l"(src), "r"(sz));
}
#define CP_COMMIT() asm volatile("cp.async.commit_group;" ::: "memory")
#define CP_WAIT1()  asm volatile("cp.async.wait_group 1;" ::: "memory")

__device__ __forceinline__ void mma8(float c[4], const uint32_t a[4],
                                     const uint32_t b[2]) {
    asm volatile(
        "mma.sync.aligned.m16n8k8.row.col.f32.tf32.tf32.f32 "
        "{%0,%1,%2,%3}, {%4,%5,%6,%7}, {%8,%9}, {%0,%1,%2,%3};"
        : "+f"(c[0]), "+f"(c[1]), "+f"(c[2]), "+f"(c[3])
        : "r"(a[0]), "r"(a[1]), "r"(a[2]), "r"(a[3]),
          "r"(b[0]), "r"(b[1]));
}

// ---------------------------------------------------------------------------
// Kernel A (to_basis): g_part[b,chunk,k,d] = sum_{v} E[v,k] * (m[v]*X[v,d])
// cp.async double-buffered 32-row stages; cvt to tf32 at frag read.
// ---------------------------------------------------------------------------
__device__ __forceinline__ void tb_issue(int sv, uint32_t* sE, uint32_t* sX,
                                         float* sMrow,
                                         const float* Eb, const float* Xb,
                                         const float* Mb, int tid) {
#pragma unroll
    for (int r = 0; r < 4; r++) {
        int idx = r * 256 + tid;          // 0..1023
        int row = idx >> 5;               // 0..31
        int c4  = idx & 31;               // 0..31
        int gv  = sv + row;
        bool p  = gv < VG;
        const float* es = p ? (Eb + (size_t)gv * KEIG + c4 * 4) : Eb;
        const float* xs = p ? (Xb + (size_t)gv * DCH  + c4 * 4) : Xb;
        cpa16(smem_u32(sE + row * TB_P + c4 * 4), es, p);
        cpa16(smem_u32(sX + row * TB_P + c4 * 4), xs, p);
    }
    if (tid < 8) {
        int o = tid * 4;
        bool p = (sv + o) < VG;
        const float* ms = p ? (Mb + sv + o) : Mb;
        cpa16(smem_u32(sMrow + o), ms, p);
    }
}

__global__ __launch_bounds__(256, 2)
void gemm_tobasis_tc(const float* __restrict__ x,
                     const float* __restrict__ mass,
                     const float* __restrict__ evecs) {
    extern __shared__ uint32_t sm[];
    uint32_t* sEb0 = sm;
    uint32_t* sXb0 = sm + TB_ROWS * TB_P;
    uint32_t* sEb1 = sm + 2 * TB_ROWS * TB_P;
    uint32_t* sXb1 = sm + 3 * TB_ROWS * TB_P;
    float*    sM   = (float*)(sm + 4 * TB_ROWS * TB_P);  // [2][32]

    const int b     = blockIdx.y;
    const int cbase = blockIdx.x * TB_CHUNK;
    const int tid   = threadIdx.x;
    const int lane  = tid & 31;
    const int wid   = tid >> 5;
    const int m0    = (wid & 1) * 64;   // k-eig offset
    const int n0    = (wid >> 1) * 32;  // d offset
    const int g     = lane >> 2;
    const int t     = lane & 3;

    const float* Eb = evecs + (size_t)b * VG * KEIG;
    const float* Xb = x     + (size_t)b * VG * DCH;
    const float* Mb = mass  + (size_t)b * VG;

    float c[4][4][4];
#pragma unroll
    for (int mi = 0; mi < 4; mi++)
#pragma unroll
        for (int ni = 0; ni < 4; ni++)
#pragma unroll
            for (int q = 0; q < 4; q++) c[mi][ni][q] = 0.f;

    tb_issue(cbase, sEb0, sXb0, sM, Eb, Xb, Mb, tid);
    CP_COMMIT();
    tb_issue(cbase + TB_ROWS, sEb1, sXb1, sM + 32, Eb, Xb, Mb, tid);
    CP_COMMIT();

    for (int s = 0; s < TB_NS; s++) {
        CP_WAIT1();
        __syncthreads();
        const uint32_t* sE = (s & 1) ? sEb1 : sEb0;
        const uint32_t* sX = (s & 1) ? sXb1 : sXb0;
        const float* sMs = sM + (s & 1) * 32;

#pragma unroll
        for (int kv = 0; kv < TB_ROWS; kv += 8) {
            const uint32_t* eLo = sE + (kv + t) * TB_P;
            const uint32_t* eHi = sE + (kv + t + 4) * TB_P;
            const uint32_t* xLo = sX + (kv + t) * TB_P;
            const uint32_t* xHi = sX + (kv + t + 4) * TB_P;
            float mLo = sMs[kv + t];
            float mHi = sMs[kv + t + 4];
            uint32_t af[4][4], bf[4][2];
#pragma unroll
            for (int mi = 0; mi < 4; mi++) {
                int mIdx = m0 + mi * 16 + g;
                af[mi][0] = f2tf32(__uint_as_float(eLo[mIdx]));
                af[mi][1] = f2tf32(__uint_as_float(eLo[mIdx + 8]));
                af[mi][2] = f2tf32(__uint_as_float(eHi[mIdx]));
                af[mi][3] = f2tf32(__uint_as_float(eHi[mIdx + 8]));
            }
#pragma unroll
            for (int ni = 0; ni < 4; ni++) {
                int nIdx = n0 + ni * 8 + g;
                bf[ni][0] = f2tf32(__uint_as_float(xLo[nIdx]) * mLo);
                bf[ni][1] = f2tf32(__uint_as_float(xHi[nIdx]) * mHi);
            }
#pragma unroll
            for (int mi = 0; mi < 4; mi++)
#pragma unroll
                for (int ni = 0; ni < 4; ni++) mma8(c[mi][ni], af[mi], bf[ni]);
        }
        __syncthreads();
        if (s + 2 < TB_NS) {
            uint32_t* dE = (s & 1) ? sEb1 : sEb0;
            uint32_t* dX = (s & 1) ? sXb1 : sXb0;
            tb_issue(cbase + (s + 2) * TB_ROWS, dE, dX, sM + (s & 1) * 32,
                     Eb, Xb, Mb, tid);
        }
        CP_COMMIT();
    }

    // epilogue: private partial slab, plain stores
    float* dst = g_part + ((size_t)(b * NCHUNK + blockIdx.x) << 14);
#pragma unroll
    for (int mi = 0; mi < 4; mi++) {
        int r0 = m0 + mi * 16 + g;
#pragma unroll
        for (int ni = 0; ni < 4; ni++) {
            int col = n0 + ni * 8 + 2 * t;
            *(float2*)&dst[r0 * DCH + col] =
                make_float2(c[mi][ni][0], c[mi][ni][1]);
            *(float2*)&dst[(r0 + 8) * DCH + col] =
                make_float2(c[mi][ni][2], c[mi][ni][3]);
        }
    }
}

// ---------------------------------------------------------------------------
// Kernel B: reduce NCHUNK partials + exp scale; store TF32 BITS transposed
// ---------------------------------------------------------------------------
__global__ void spectral_reduce_scale(const float* __restrict__ evals,
                                      const float* __restrict__ tdiff) {
    int i = blockIdx.x * 256 + threadIdx.x;   // over b*K*D
    if (i >= BGR * KEIG * DCH) return;
    int d = i & 127;
    int k = (i >> 7) & 127;
    int b = i >> 14;
    const float* p = g_part + ((size_t)(b * NCHUNK) << 14) + k * DCH + d;
    float s = 0.f;
#pragma unroll
    for (int ch = 0; ch < NCHUNK; ch++) s += p[(size_t)ch << 14];
    float tt = fmaxf(tdiff[d], 1e-8f);
    float val = s * expf(-evals[b * KEIG + k] * tt);
    g_shat_T[(b << 14) + (d << 7) + k] = __uint_as_float(f2tf32(val));
}

// ---------------------------------------------------------------------------
// Kernel C (from_basis): out[v,d] = sum_k E[v,k] * S_T[d,k]
// 4 k-chunks of 32, cp.async double-buffered. S already tf32 (no cvt);
// E converts at frag read.
// ---------------------------------------------------------------------------
__device__ __forceinline__ void fb_issue(int k0, uint32_t* sE, uint32_t* sS,
                                         const float* Eb, const float* Sb,
                                         int v0, int tid) {
#pragma unroll
    for (int r = 0; r < 4; r++) {
        int idx = r * 256 + tid;          // 0..1023
        int row = idx >> 3;               // 0..127
        int c4  = idx & 7;                // 0..7
        cpa16(smem_u32(sS + row * FB_P + c4 * 4),
              Sb + (size_t)row * KEIG + k0 + c4 * 4, true);
        int v = v0 + row;
        bool p = v < VG;
        const float* es = p ? (Eb + (size_t)v * KEIG + k0 + c4 * 4) : Eb;
        cpa16(smem_u32(sE + row * FB_P + c4 * 4), es, p);
    }
}

__global__ __launch_bounds__(256, 2)
void gemm_frombasis_tc(const float* __restrict__ evecs,
                       float* __restrict__ out) {
    extern __shared__ uint32_t sm[];
    uint32_t* sEb0 = sm;
    uint32_t* sSb0 = sm + 128 * FB_P;
    uint32_t* sEb1 = sm + 2 * 128 * FB_P;
    uint32_t* sSb1 = sm + 3 * 128 * FB_P;

    const int b    = blockIdx.y;
    const int v0   = blockIdx.x * 128;
    const int tid  = threadIdx.x;
    const int lane = tid & 31;
    const int wid  = tid >> 5;
    const int m0   = (wid & 1) * 64;    // v offset
    const int n0   = (wid >> 1) * 32;   // d offset
    const int g    = lane >> 2;
    const int t    = lane & 3;

    const float* Eb = evecs    + (size_t)b * VG * KEIG;
    const float* Sb = g_shat_T + ((size_t)b << 14);

    float c[4][4][4];
#pragma unroll
    for (int mi = 0; mi < 4; mi++)
#pragma unroll
        for (int ni = 0; ni < 4; ni++)
#pragma unroll
            for (int q = 0; q < 4; q++) c[mi][ni][q] = 0.f;

    fb_issue(0, sEb0, sSb0, Eb, Sb, v0, tid);
    CP_COMMIT();
    fb_issue(FB_KC, sEb1, sSb1, Eb, Sb, v0, tid);
    CP_COMMIT();

#pragma unroll
    for (int ck = 0; ck < 4; ck++) {
        CP_WAIT1();
        __syncthreads();
        const uint32_t* sE = (ck & 1) ? sEb1 : sEb0;
        const uint32_t* sS = (ck & 1) ? sSb1 : sSb0;

#pragma unroll
        for (int ks = 0; ks < FB_KC; ks += 8) {
            uint32_t af[4][4], bf[4][2];
#pragma unroll
            for (int mi = 0; mi < 4; mi++) {
                const uint32_t* p = sE + (m0 + mi * 16 + g) * FB_P + ks + t;
                af[mi][0] = f2tf32(__uint_as_float(p[0]));
                af[mi][1] = f2tf32(__uint_as_float(p[8 * FB_P]));
                af[mi][2] = f2tf32(__uint_as_float(p[4]));
                af[mi][3] = f2tf32(__uint_as_float(p[8 * FB_P + 4]));
            }
#pragma unroll
            for (int ni = 0; ni < 4; ni++) {
                const uint32_t* p = sS + (n0 + ni * 8 + g) * FB_P + ks + t;
                bf[ni][0] = p[0];
                bf[ni][1] = p[4];
            }
#pragma unroll
            for (int mi = 0; mi < 4; mi++)
#pragma unroll
                for (int ni = 0; ni < 4; ni++) mma8(c[mi][ni], af[mi], bf[ni]);
        }
        __syncthreads();
        if (ck + 2 < 4) {
            uint32_t* dE = (ck & 1) ? sEb1 : sEb0;
            uint32_t* dS = (ck & 1) ? sSb1 : sSb0;
            fb_issue((ck + 2) * FB_KC, dE, dS, Eb, Sb, v0, tid);
        }
        CP_COMMIT();
    }

    // epilogue: direct, sector-aligned float2 stores
#pragma unroll
    for (int mi = 0; mi < 4; mi++) {
        int vlo = v0 + m0 + mi * 16 + g;
#pragma unroll
        for (int ni = 0; ni < 4; ni++) {
            int col = n0 + ni * 8 + 2 * t;
            if (vlo < VG)
                *(float2*)(out + (size_t)(b * VG + vlo) * DCH + col) =
                    make_float2(c[mi][ni][0], c[mi][ni][1]);
            if (vlo + 8 < VG)
                *(float2*)(out + (size_t)(b * VG + vlo + 8) * DCH + col) =
                    make_float2(c[mi][ni][2], c[mi][ni][3]);
        }
    }
}

// ---------------------------------------------------------------------------
// Launch
// Inputs: 0:x (V,D) f32, 1:mass (V,) f32, 2:evals (B*K,) f32,
// 3:evecs (V,K) f32, 4:diffusion_time (D,) f32, 5:batch (V,) i32, 6:bs
// Output: (V,D) f32
// ---------------------------------------------------------------------------
extern "C" void kernel_launch(void* const* d_in, const int* in_sizes, int n_in,
                              void* d_out, int out_size) {
    const float* x     = (const float*)d_in[0];
    const float* mass  = (const float*)d_in[1];
    const float* evals = (const float*)d_in[2];
    const float* evecs = (const float*)d_in[3];
    const float* tdiff = (const float*)d_in[4];
    float* out = (float*)d_out;

    (void)in_sizes; (void)n_in; (void)out_size;

    const int TB_SMEM = (4 * TB_ROWS * TB_P + 64) * 4;   // 69888 B
    const int FB_SMEM = (4 * 128 * FB_P) * 4;            // 73728 B
    cudaFuncSetAttribute(gemm_tobasis_tc,
                         cudaFuncAttributeMaxDynamicSharedMemorySize, TB_SMEM);
    cudaFuncSetAttribute(gemm_frombasis_tc,
                         cudaFuncAttributeMaxDynamicSharedMemorySize, FB_SMEM);

    dim3 gridA(NCHUNK, BGR);
    gemm_tobasis_tc<<<gridA, 256, TB_SMEM>>>(x, mass, evecs);

    spectral_reduce_scale<<<(BGR * KEIG * DCH + 255) / 256, 256>>>(evals, tdiff);

    dim3 gridC((VG + 127) / 128, BGR);
    gemm_frombasis_tc<<<gridC, 256, FB_SMEM>>>(evecs, out);
}

// round 10
// speedup vs baseline: 3.3967x; 1.0484x over previous
#include <cuda_runtime.h>
#include <cstdint>
#include <math.h>

// Problem constants (fixed by the dataset)
#define VG   20000
#define BGR  8
#define KEIG 128
#define DCH  128

#define NCHUNK   37      // 37 chunks x 8 graphs = 296 CTAs = one 2-CTA/SM wave
#define TB_CHUNK 544     // 37 * 544 = 20128 >= 20000
#define TB_ROWS  32      // v-rows per stage
#define TB_NS    17      // stages per chunk
#define TB_P     136     // pitch: conflict-free (t*136+g) frag reads + row staging
#define TB_BUFELEMS (2 * TB_ROWS * TB_P)   // sE+sX per stage (uint32 elems)

#define FB_KC    32      // k per chunk in from_basis
#define FB_NCK   4       // k chunks
#define FB_P     36      // pitch: conflict-free frag reads + row staging
#define FB_BUFELEMS (2 * 128 * FB_P)

// Scratch (device globals — no allocations)
__device__ float g_part[BGR * NCHUNK * KEIG * DCH];  // per-chunk partial x_spec
__device__ float g_shat_T[BGR * DCH * KEIG];         // scaled spectrum, tf32 bits, [b][d][k]

// ---------------------------------------------------------------------------
// helpers
// ---------------------------------------------------------------------------
__device__ __forceinline__ uint32_t f2tf32(float x) {
    uint32_t r;
    asm("cvt.rna.tf32.f32 %0, %1;" : "=r"(r) : "f"(x));
    return r;
}
__device__ __forceinline__ uint32_t smem_u32(const void* p) {
    uint32_t a;
    asm("{ .reg .u64 t; cvta.to.shared.u64 t, %1; cvt.u32.u64 %0, t; }"
        : "=r"(a) : "l"(p));
    return a;
}
// 16B async copy; zero-fill (sz=0) when pred==false (src must stay valid)
__device__ __forceinline__ void cpa16(uint32_t dst, const void* src, bool pred) {
    int sz = pred ? 16 : 0;
    asm volatile("cp.async.cg.shared.global [%0], [%1], 16, %2;"
                 :: "r"(dst), "l"(src), "r"(sz));
}
#define CP_COMMIT() asm volatile("cp.async.commit_group;" ::: "memory")
#define CP_WAIT2()  asm volatile("cp.async.wait_group 2;" ::: "memory")

__device__ __forceinline__ void mma8(float c[4], const uint32_t a[4],
                                     const uint32_t b[2]) {
    asm volatile(
        "mma.sync.aligned.m16n8k8.row.col.f32.tf32.tf32.f32 "
        "{%0,%1,%2,%3}, {%4,%5,%6,%7}, {%8,%9}, {%0,%1,%2,%3};"
        : "+f"(c[0]), "+f"(c[1]), "+f"(c[2]), "+f"(c[3])
        : "r"(a[0]), "r"(a[1]), "r"(a[2]), "r"(a[3]),
          "r"(b[0]), "r"(b[1]));
}

// ---------------------------------------------------------------------------
// Kernel A (to_basis): g_part[b,chunk,k,d] = sum_{v} E[v,k] * (m[v]*X[v,d])
// 3-stage cp.async pipeline, 32-row stages; cvt to tf32 at frag read.
// smem/CTA = 3*(sE+sX) + 3*32 mass = 102.8KB -> 2 CTA/SM.
// ---------------------------------------------------------------------------
__device__ __forceinline__ void tb_issue(int sv, uint32_t uE, uint32_t uX,
                                         uint32_t uM,
                                         const float* Eb, const float* Xb,
                                         const float* Mb, int tid) {
#pragma unroll
    for (int r = 0; r < 4; r++) {
        int idx = r * 256 + tid;          // 0..1023
        int row = idx >> 5;               // 0..31
        int c4  = idx & 31;               // 0..31
        int gv  = sv + row;
        bool p  = gv < VG;
        const float* es = p ? (Eb + (size_t)gv * KEIG + c4 * 4) : Eb;
        const float* xs = p ? (Xb + (size_t)gv * DCH  + c4 * 4) : Xb;
        uint32_t off = (uint32_t)(row * TB_P + c4 * 4) * 4u;
        cpa16(uE + off, es, p);
        cpa16(uX + off, xs, p);
    }
    if (tid < 8) {
        int o = tid * 4;
        bool p = (sv + o) < VG;
        const float* ms = p ? (Mb + sv + o) : Mb;
        cpa16(uM + o * 4u, ms, p);
    }
}

__global__ __launch_bounds__(256, 2)
void gemm_tobasis_tc(const float* __restrict__ x,
                     const float* __restrict__ mass,
                     const float* __restrict__ evecs) {
    extern __shared__ uint32_t sm[];
    // layout: 3 x [sE(32*136) | sX(32*136)], then mass[3][32]
    float* sMall = (float*)(sm + 3 * TB_BUFELEMS);
    const uint32_t uBase = smem_u32(sm);
    const uint32_t uMbase = smem_u32(sMall);

    const int b     = blockIdx.y;
    const int cbase = blockIdx.x * TB_CHUNK;
    const int tid   = threadIdx.x;
    const int lane  = tid & 31;
    const int wid   = tid >> 5;
    const int m0    = (wid & 1) * 64;   // k-eig offset
    const int n0    = (wid >> 1) * 32;  // d offset
    const int g     = lane >> 2;
    const int t     = lane & 3;

    const float* Eb = evecs + (size_t)b * VG * KEIG;
    const float* Xb = x     + (size_t)b * VG * DCH;
    const float* Mb = mass  + (size_t)b * VG;

    float c[4][4][4];
#pragma unroll
    for (int mi = 0; mi < 4; mi++)
#pragma unroll
        for (int ni = 0; ni < 4; ni++)
#pragma unroll
            for (int q = 0; q < 4; q++) c[mi][ni][q] = 0.f;

    // prologue: fill 3 stages
#pragma unroll
    for (int s = 0; s < 3; s++) {
        tb_issue(cbase + s * TB_ROWS,
                 uBase + (uint32_t)(s * TB_BUFELEMS) * 4u,
                 uBase + (uint32_t)(s * TB_BUFELEMS + TB_ROWS * TB_P) * 4u,
                 uMbase + (uint32_t)(s * 32) * 4u,
                 Eb, Xb, Mb, tid);
        CP_COMMIT();
    }

    int bi = 0;
    for (int s = 0; s < TB_NS; s++) {
        CP_WAIT2();
        __syncthreads();
        const uint32_t* sE = sm + bi * TB_BUFELEMS;
        const uint32_t* sX = sE + TB_ROWS * TB_P;
        const float* sMs = sMall + bi * 32;

#pragma unroll
        for (int kv = 0; kv < TB_ROWS; kv += 8) {
            const uint32_t* eLo = sE + (kv + t) * TB_P;
            const uint32_t* eHi = sE + (kv + t + 4) * TB_P;
            const uint32_t* xLo = sX + (kv + t) * TB_P;
            const uint32_t* xHi = sX + (kv + t + 4) * TB_P;
            float mLo = sMs[kv + t];
            float mHi = sMs[kv + t + 4];
            uint32_t af[4][4], bf[4][2];
#pragma unroll
            for (int mi = 0; mi < 4; mi++) {
                int mIdx = m0 + mi * 16 + g;
                af[mi][0] = f2tf32(__uint_as_float(eLo[mIdx]));
                af[mi][1] = f2tf32(__uint_as_float(eLo[mIdx + 8]));
                af[mi][2] = f2tf32(__uint_as_float(eHi[mIdx]));
                af[mi][3] = f2tf32(__uint_as_float(eHi[mIdx + 8]));
            }
#pragma unroll
            for (int ni = 0; ni < 4; ni++) {
                int nIdx = n0 + ni * 8 + g;
                bf[ni][0] = f2tf32(__uint_as_float(xLo[nIdx]) * mLo);
                bf[ni][1] = f2tf32(__uint_as_float(xHi[nIdx]) * mHi);
            }
#pragma unroll
            for (int mi = 0; mi < 4; mi++)
#pragma unroll
                for (int ni = 0; ni < 4; ni++) mma8(c[mi][ni], af[mi], bf[ni]);
        }
        __syncthreads();
        if (s + 3 < TB_NS) {
            tb_issue(cbase + (s + 3) * TB_ROWS,
                     uBase + (uint32_t)(bi * TB_BUFELEMS) * 4u,
                     uBase + (uint32_t)(bi * TB_BUFELEMS + TB_ROWS * TB_P) * 4u,
                     uMbase + (uint32_t)(bi * 32) * 4u,
                     Eb, Xb, Mb, tid);
        }
        CP_COMMIT();
        if (++bi == 3) bi = 0;
    }

    // epilogue: private partial slab, plain stores
    float* dst = g_part + ((size_t)(b * NCHUNK + blockIdx.x) << 14);
#pragma unroll
    for (int mi = 0; mi < 4; mi++) {
        int r0 = m0 + mi * 16 + g;
#pragma unroll
        for (int ni = 0; ni < 4; ni++) {
            int col = n0 + ni * 8 + 2 * t;
            *(float2*)&dst[r0 * DCH + col] =
                make_float2(c[mi][ni][0], c[mi][ni][1]);
            *(float2*)&dst[(r0 + 8) * DCH + col] =
                make_float2(c[mi][ni][2], c[mi][ni][3]);
        }
    }
}

// ---------------------------------------------------------------------------
// Kernel B: reduce NCHUNK partials + exp scale; store TF32 BITS transposed
// ---------------------------------------------------------------------------
__global__ void spectral_reduce_scale(const float* __restrict__ evals,
                                      const float* __restrict__ tdiff) {
    int i = blockIdx.x * 256 + threadIdx.x;   // over b*K*D
    if (i >= BGR * KEIG * DCH) return;
    int d = i & 127;
    int k = (i >> 7) & 127;
    int b = i >> 14;
    const float* p = g_part + ((size_t)(b * NCHUNK) << 14) + k * DCH + d;
    float s = 0.f;
#pragma unroll
    for (int ch = 0; ch < NCHUNK; ch++) s += p[(size_t)ch << 14];
    float tt = fmaxf(tdiff[d], 1e-8f);
    float val = s * expf(-evals[b * KEIG + k] * tt);
    g_shat_T[(b << 14) + (d << 7) + k] = __uint_as_float(f2tf32(val));
}

// ---------------------------------------------------------------------------
// Kernel C (from_basis): out[v,d] = sum_k E[v,k] * S_T[d,k]
// 4 k-chunks of 32, 3-stage cp.async pipeline. S already tf32 (no cvt).
// smem/CTA = 3 * 36KB = 108KB -> 2 CTA/SM.
// ---------------------------------------------------------------------------
__device__ __forceinline__ void fb_issue(int k0, uint32_t uE, uint32_t uS,
                                         const float* Eb, const float* Sb,
                                         int v0, int tid) {
#pragma unroll
    for (int r = 0; r < 4; r++) {
        int idx = r * 256 + tid;          // 0..1023
        int row = idx >> 3;               // 0..127
        int c4  = idx & 7;                // 0..7
        uint32_t off = (uint32_t)(row * FB_P + c4 * 4) * 4u;
        cpa16(uS + off, Sb + (size_t)row * KEIG + k0 + c4 * 4, true);
        int v = v0 + row;
        bool p = v < VG;
        const float* es = p ? (Eb + (size_t)v * KEIG + k0 + c4 * 4) : Eb;
        cpa16(uE + off, es, p);
    }
}

__global__ __launch_bounds__(256, 2)
void gemm_frombasis_tc(const float* __restrict__ evecs,
                       float* __restrict__ out) {
    extern __shared__ uint32_t sm[];
    const uint32_t uBase = smem_u32(sm);

    const int b    = blockIdx.y;
    const int v0   = blockIdx.x * 128;
    const int tid  = threadIdx.x;
    const int lane = tid & 31;
    const int wid  = tid >> 5;
    const int m0   = (wid & 1) * 64;    // v offset
    const int n0   = (wid >> 1) * 32;   // d offset
    const int g    = lane >> 2;
    const int t    = lane & 3;

    const float* Eb = evecs    + (size_t)b * VG * KEIG;
    const float* Sb = g_shat_T + ((size_t)b << 14);

    float c[4][4][4];
#pragma unroll
    for (int mi = 0; mi < 4; mi++)
#pragma unroll
        for (int ni = 0; ni < 4; ni++)
#pragma unroll
            for (int q = 0; q < 4; q++) c[mi][ni][q] = 0.f;

    // prologue: fill 3 of 4 chunks
#pragma unroll
    for (int s = 0; s < 3; s++) {
        fb_issue(s * FB_KC,
                 uBase + (uint32_t)(s * FB_BUFELEMS) * 4u,
                 uBase + (uint32_t)(s * FB_BUFELEMS + 128 * FB_P) * 4u,
                 Eb, Sb, v0, tid);
        CP_COMMIT();
    }

    int bi = 0;
#pragma unroll
    for (int ck = 0; ck < FB_NCK; ck++) {
        CP_WAIT2();
        __syncthreads();
        const uint32_t* sE = sm + bi * FB_BUFELEMS;
        const uint32_t* sS = sE + 128 * FB_P;

#pragma unroll
        for (int ks = 0; ks < FB_KC; ks += 8) {
            uint32_t af[4][4], bf[4][2];
#pragma unroll
            for (int mi = 0; mi < 4; mi++) {
                const uint32_t* p = sE + (m0 + mi * 16 + g) * FB_P + ks + t;
                af[mi][0] = f2tf32(__uint_as_float(p[0]));
                af[mi][1] = f2tf32(__uint_as_float(p[8 * FB_P]));
                af[mi][2] = f2tf32(__uint_as_float(p[4]));
                af[mi][3] = f2tf32(__uint_as_float(p[8 * FB_P + 4]));
            }
#pragma unroll
            for (int ni = 0; ni < 4; ni++) {
                const uint32_t* p = sS + (n0 + ni * 8 + g) * FB_P + ks + t;
                bf[ni][0] = p[0];
                bf[ni][1] = p[4];
            }
#pragma unroll
            for (int mi = 0; mi < 4; mi++)
#pragma unroll
                for (int ni = 0; ni < 4; ni++) mma8(c[mi][ni], af[mi], bf[ni]);
        }
        __syncthreads();
        if (ck + 3 < FB_NCK) {
            fb_issue((ck + 3) * FB_KC,
                     uBase + (uint32_t)(bi * FB_BUFELEMS) * 4u,
                     uBase + (uint32_t)(bi * FB_BUFELEMS + 128 * FB_P) * 4u,
                     Eb, Sb, v0, tid);
        }
        CP_COMMIT();
        if (++bi == 3) bi = 0;
    }

    // epilogue: direct, sector-aligned float2 stores
#pragma unroll
    for (int mi = 0; mi < 4; mi++) {
        int vlo = v0 + m0 + mi * 16 + g;
#pragma unroll
        for (int ni = 0; ni < 4; ni++) {
            int col = n0 + ni * 8 + 2 * t;
            if (vlo < VG)
                *(float2*)(out + (size_t)(b * VG + vlo) * DCH + col) =
                    make_float2(c[mi][ni][0], c[mi][ni][1]);
            if (vlo + 8 < VG)
                *(float2*)(out + (size_t)(b * VG + vlo + 8) * DCH + col) =
                    make_float2(c[mi][ni][2], c[mi][ni][3]);
        }
    }
}

// ---------------------------------------------------------------------------
// Launch
// Inputs: 0:x (V,D) f32, 1:mass (V,) f32, 2:evals (B*K,) f32,
// 3:evecs (V,K) f32, 4:diffusion_time (D,) f32, 5:batch (V,) i32, 6:bs
// Output: (V,D) f32
// ---------------------------------------------------------------------------
extern "C" void kernel_launch(void* const* d_in, const int* in_sizes, int n_in,
                              void* d_out, int out_size) {
    const float* x     = (const float*)d_in[0];
    const float* mass  = (const float*)d_in[1];
    const float* evals = (const float*)d_in[2];
    const float* evecs = (const float*)d_in[3];
    const float* tdiff = (const float*)d_in[4];
    float* out = (float*)d_out;

    (void)in_sizes; (void)n_in; (void)out_size;

    const int TB_SMEM = (3 * TB_BUFELEMS + 3 * 32) * 4;  // 104832 B
    const int FB_SMEM = (3 * FB_BUFELEMS) * 4;           // 110592 B
    cudaFuncSetAttribute(gemm_tobasis_tc,
                         cudaFuncAttributeMaxDynamicSharedMemorySize, TB_SMEM);
    cudaFuncSetAttribute(gemm_frombasis_tc,
                         cudaFuncAttributeMaxDynamicSharedMemorySize, FB_SMEM);

    dim3 gridA(NCHUNK, BGR);
    gemm_tobasis_tc<<<gridA, 256, TB_SMEM>>>(x, mass, evecs);

    spectral_reduce_scale<<<(BGR * KEIG * DCH + 255) / 256, 256>>>(evals, tdiff);

    dim3 gridC((VG + 127) / 128, BGR);
    gemm_frombasis_tc<<<gridC, 256, FB_SMEM>>>(evecs, out);
}